// round 13
// baseline (speedup 1.0000x reference)
#include <cstdint>
#include <cstddef>
#include <cuda_runtime.h>
#include <cuda_fp16.h>
#include <mma.h>

using namespace nvcuda;

#define BSZ 128
#define TT  128
#define INP 64
#define HID 512
#define G4  2048
#define HB  (BSZ*HID)
#define NCTA 128

// smem map (bytes):
//   [0, 99328)        cell weights: 64 rows x <=768 halves, stride 776h (1552B)
//   [99328, 133120)   WX (bottom only): 64 rows x 256 halves, stride 264h (528B)
//   [133120, 185344)  A ring: 3 x 17408B (64 rows x 128 halves, stride 136h)
//   [185344, 218112)  smf: 2 (k-groups) x 64x64 float
#define WSTRH   776
#define WSTRB   1552
#define WXOFF   99328
#define WXSTRH  264
#define WXSTRB  528
#define AOFF    133120
#define ASTRH   136
#define ASTRB   272
#define ABSZ    17408
#define SMFOFF  185344
#define SMEM_TOTAL 218112

__device__ __align__(128) __half g_eWih0[G4*INP];
__device__ __align__(128) __half g_eWhh0[G4*HID];
__device__ __align__(128) __half g_eWih1[G4*HID];
__device__ __align__(128) __half g_eWhh1[G4*HID];
__device__ __align__(128) __half g_dWih0[G4*HID];
__device__ __align__(128) __half g_dWhh0[G4*HID];
__device__ __align__(128) __half g_dWih1[G4*HID];
__device__ __align__(128) __half g_dWhh1[G4*HID];
__device__ __align__(128) __half g_fcW[INP*HID];
__device__ float  g_be0[G4];
__device__ float  g_be1[G4];
__device__ float  g_bd0[G4];
__device__ float  g_bd1[G4];
__device__ __align__(128) __half g_x16[TT*BSZ*INP];
__device__ __align__(128) __half g_h0[2][HB];
__device__ __align__(128) __half g_h1[2][HB];
__device__ __align__(128) __half g_hd0[2][HB];
__device__ __align__(128) __half g_hd1[2][HB];
__device__ float  g_gx[BSZ*G4];
__device__ __align__(128) float g_px[2*64*4096];   // [parity][pair lb][64x64]
__device__ __align__(128) __half g_hs[TT*BSZ*HID];
__device__ unsigned g_ctr;
__device__ unsigned g_flag[8];
__device__ unsigned g_pxf[128];   // [0:64) enc pair flags, [64:128) dec

// ---------------- prep ----------------
__global__ void prep_kernel(
    const float* __restrict__ x,
    const float* __restrict__ eWih0, const float* __restrict__ eWhh0,
    const float* __restrict__ ebih0, const float* __restrict__ ebhh0,
    const float* __restrict__ eWih1, const float* __restrict__ eWhh1,
    const float* __restrict__ ebih1, const float* __restrict__ ebhh1,
    const float* __restrict__ dWih0, const float* __restrict__ dWhh0,
    const float* __restrict__ dbih0, const float* __restrict__ dbhh0,
    const float* __restrict__ dWih1, const float* __restrict__ dWhh1,
    const float* __restrict__ dbih1, const float* __restrict__ dbhh1,
    const float* __restrict__ fcW)
{
    const long NP = 8822921;
    long stride = (long)gridDim.x * blockDim.x;
    for (long i = (long)blockIdx.x * blockDim.x + threadIdx.x; i < NP; i += stride) {
        long r = i;
        if (r < 131072)  { g_eWih0[r] = __float2half(eWih0[r]); continue; } r -= 131072;
        if (r < 1048576) { g_eWhh0[r] = __float2half(eWhh0[r]); continue; } r -= 1048576;
        if (r < 1048576) { g_eWih1[r] = __float2half(eWih1[r]); continue; } r -= 1048576;
        if (r < 1048576) { g_eWhh1[r] = __float2half(eWhh1[r]); continue; } r -= 1048576;
        if (r < 1048576) { g_dWih0[r] = __float2half(dWih0[r]); continue; } r -= 1048576;
        if (r < 1048576) { g_dWhh0[r] = __float2half(dWhh0[r]); continue; } r -= 1048576;
        if (r < 1048576) { g_dWih1[r] = __float2half(dWih1[r]); continue; } r -= 1048576;
        if (r < 1048576) { g_dWhh1[r] = __float2half(dWhh1[r]); continue; } r -= 1048576;
        if (r < 32768)   { g_fcW[r]   = __float2half(fcW[r]);   continue; } r -= 32768;
        if (r < 8192) {
            int which = (int)(r >> 11);
            int j = (int)(r & 2047);
            if      (which == 0) g_be0[j] = ebih0[j] + ebhh0[j];
            else if (which == 1) g_be1[j] = ebih1[j] + ebhh1[j];
            else if (which == 2) g_bd0[j] = dbih0[j] + dbhh0[j];
            else                 g_bd1[j] = dbih1[j] + dbhh1[j];
            continue;
        } r -= 8192;
        if (r < 1048576) {
            int t = (int)(r >> 13);
            int rem = (int)(r & 8191);
            int b = rem >> 6;
            int k = rem & 63;
            g_x16[r] = __float2half(x[(size_t)b * TT * INP + (size_t)t * INP + k]);
            continue;
        } r -= 1048576;
        if (r < 262144) {
            int which = (int)(r >> 16);
            int j = (int)(r & 65535);
            __half z = __float2half(0.f);
            if      (which == 0) g_h0[1][j]  = z;
            else if (which == 1) g_h1[1][j]  = z;
            else if (which == 2) g_hd0[1][j] = z;
            else                 g_hd1[1][j] = z;
            continue;
        } r -= 262144;
        {   // 137 sync words
            if      (r < 8)   g_flag[r] = 0u;
            else if (r < 136) g_pxf[r - 8] = 0u;
            else              g_ctr = 0u;
        }
    }
}

// ---------------- helpers ----------------
__device__ __forceinline__ void cp_async16(uint32_t dst_smem, const void* src) {
    asm volatile("cp.async.cg.shared.global [%0], [%1], 16;"
                 :: "r"(dst_smem), "l"(src) : "memory");
}
__device__ __forceinline__ void cp_async_commit() {
    asm volatile("cp.async.commit_group;" ::: "memory");
}
__device__ __forceinline__ void cp_async_wait0() {
    asm volatile("cp.async.wait_group 0;" ::: "memory");
}
__device__ __forceinline__ void cp_async_wait1() {
    asm volatile("cp.async.wait_group 1;" ::: "memory");
}
__device__ __forceinline__ uint32_t smem_to_u32(const void* smem_ptr) {
    uint32_t addr;
    asm("{ .reg .u64 tmp; cvta.to.shared.u64 tmp, %1; cvt.u32.u64 %0, tmp; }"
        : "=r"(addr) : "l"(smem_ptr));
    return addr;
}
__device__ __forceinline__ float sigf(float v) { return 1.f / (1.f + __expf(-v)); }

__device__ __forceinline__ void grid_sync(unsigned target) {
    __syncthreads();
    if (threadIdx.x == 0) {
        __threadfence();
        atomicAdd(&g_ctr, 1u);
        volatile unsigned* cp = &g_ctr;
        while (*cp < target) { }
        __threadfence();
    }
    __syncthreads();
}
__device__ __forceinline__ void waitflag(unsigned* f, unsigned v) {
    if (threadIdx.x == 0) {
        volatile unsigned* p = f;
        while (*p < v) { }
        __threadfence();
    }
    __syncthreads();
}
__device__ __forceinline__ void post_flag(unsigned* f) {
    __syncthreads();
    if (threadIdx.x == 0) {
        __threadfence();
        atomicAdd(f, 1u);
    }
}

// ---------------- stationary weight loads ----------------
// smem row c: weight row grow = (c&3)*512 + u0 + (c>>2); cols = [W1[off1:off1+K1] | W2]
__device__ void load_wsm(char* smraw, const __half* __restrict__ W1, int ld1, int off1,
                         int K1, const __half* __restrict__ W2, int Ktot, int u0) {
    int ng = Ktot >> 3;
    int tot = 64 * ng;
    for (int idx = threadIdx.x; idx < tot; idx += 256) {
        int c = idx / ng;
        int gi = idx - c * ng;
        int k = gi << 3;
        int grow = (c & 3) * 512 + u0 + (c >> 2);
        uint4 v;
        if (k < K1) v = *(const uint4*)(W1 + (size_t)grow * ld1 + off1 + k);
        else        v = *(const uint4*)(W2 + (size_t)grow * 512 + (k - K1));
        *(uint4*)(smraw + (size_t)c * WSTRB + ((size_t)k << 1)) = v;
    }
}
// pair-top Wih slice cols [0:256)
__device__ void load_wx(char* smraw, const __half* __restrict__ W, int u0) {
    for (int idx = threadIdx.x; idx < 64 * 32; idx += 256) {
        int c = idx >> 5;
        int gi = idx & 31;
        int k = gi << 3;
        int grow = (c & 3) * 512 + u0 + (c >> 2);
        *(uint4*)(smraw + WXOFF + (size_t)c * WXSTRB + ((size_t)k << 1)) =
            *(const uint4*)(W + (size_t)grow * 512 + k);
    }
}

// ---------------- stage one A chunk (cols in {128,64}) ----------------
__device__ __forceinline__ void stage_chunk(uint32_t dst, int kb, int cols,
                                            const __half* __restrict__ s0, int ld0, int Kx,
                                            const __half* __restrict__ s1, int m0) {
    if (cols == 128) {
#pragma unroll
        for (int i = 0; i < 4; i++) {
            int idx = (int)threadIdx.x + i * 256;
            int r = idx >> 4;
            int gi = idx & 15;
            int k = kb + (gi << 3);
            const __half* src = (k < Kx) ? (s0 + (size_t)(m0 + r) * ld0 + k)
                                         : (s1 + (size_t)(m0 + r) * HID + (k - Kx));
            cp_async16(dst + (uint32_t)(r * ASTRB + (gi << 4)), src);
        }
    } else {
#pragma unroll
        for (int i = 0; i < 2; i++) {
            int idx = (int)threadIdx.x + i * 256;
            int r = idx >> 3;
            int gi = idx & 7;
            int k = kb + (gi << 3);
            const __half* src = (k < Kx) ? (s0 + (size_t)(m0 + r) * ld0 + k)
                                         : (s1 + (size_t)(m0 + r) * HID + (k - Kx));
            cp_async16(dst + (uint32_t)(r * ASTRB + (gi << 4)), src);
        }
    }
}

// ---------------- LSTM cell step (8 warps = kg2 x mi2 x ni2, 32x32 tiles) ----------------
__device__ __forceinline__ void cell_step(
    char* smraw, uint32_t smb,
    const __half* __restrict__ s0, int ld0, int Kx,
    const __half* __restrict__ s1, int K,
    const float* badd, float* cst,
    __half* __restrict__ hout, __half* __restrict__ hsave,
    int m0, int u0, int kg, int mi, int ni, int uloc, int mb,
    unsigned* wB, unsigned vB,
    unsigned* wE, unsigned vE,
    unsigned* pxf, unsigned vP, const float* __restrict__ pxsrc)
{
    wmma::fragment<wmma::accumulator, 16, 16, 16, float> a00, a01, a10, a11;
    wmma::fill_fragment(a00, 0.f);
    wmma::fill_fragment(a01, 0.f);
    wmma::fill_fragment(a10, 0.f);
    wmma::fill_fragment(a11, 0.f);
    wmma::fragment<wmma::matrix_a, 16, 16, 16, __half, wmma::row_major> af0, af1;
    wmma::fragment<wmma::matrix_b, 16, 16, 16, __half, wmma::col_major> bf0, bf1;

    int nch = (K + 127) >> 7;
    {
        stage_chunk(smb + AOFF, 0, (K < 128) ? K : 128, s0, ld0, Kx, s1, m0);
        cp_async_commit();
        if (nch > 1) {
            int c1 = K - 128; if (c1 > 128) c1 = 128;
            stage_chunk(smb + AOFF + ABSZ, 128, c1, s0, ld0, Kx, s1, m0);
            cp_async_commit();
        }
    }
    int buf = 0;
    for (int i = 0; i < nch; ++i) {
        if (wB && i == 0) waitflag(wB, vB);
        if (i + 1 < nch) cp_async_wait1(); else cp_async_wait0();
        __syncthreads();
        if (i + 2 < nch) {
            int kb2 = (i + 2) << 7;
            int c2 = K - kb2; if (c2 > 128) c2 = 128;
            int buf2 = buf + 2; if (buf2 >= 3) buf2 -= 3;
            stage_chunk(smb + AOFF + (uint32_t)buf2 * ABSZ, kb2, c2, s0, ld0, Kx, s1, m0);
            cp_async_commit();
        }
        int kb = i << 7;
        int cols = K - kb; if (cols > 128) cols = 128;
        const __half* abase = (const __half*)(smraw + AOFF + (size_t)buf * ABSZ)
                            + (size_t)(mi * 32) * ASTRH;
        const __half* bbase = (const __half*)smraw + (size_t)(ni * 32) * WSTRH + kb;
        int half = cols >> 5;
#pragma unroll 4
        for (int s = 0; s < half; ++s) {
            int kk = (kg * half + s) << 4;
            wmma::load_matrix_sync(af0, abase + kk, ASTRH);
            wmma::load_matrix_sync(af1, abase + 16 * ASTRH + kk, ASTRH);
            wmma::load_matrix_sync(bf0, bbase + kk, WSTRH);
            wmma::load_matrix_sync(bf1, bbase + 16 * WSTRH + kk, WSTRH);
            wmma::mma_sync(a00, af0, bf0, a00);
            wmma::mma_sync(a01, af0, bf1, a01);
            wmma::mma_sync(a10, af1, bf0, a10);
            wmma::mma_sync(a11, af1, bf1, a11);
        }
        buf = buf + 1; if (buf >= 3) buf = 0;
    }

    float* smf = (float*)(smraw + SMFOFF) + (size_t)kg * 4096;
    wmma::store_matrix_sync(smf + (size_t)(mi * 32) * 64 + ni * 32,           a00, 64, wmma::mem_row_major);
    wmma::store_matrix_sync(smf + (size_t)(mi * 32) * 64 + ni * 32 + 16,      a01, 64, wmma::mem_row_major);
    wmma::store_matrix_sync(smf + (size_t)(mi * 32 + 16) * 64 + ni * 32,      a10, 64, wmma::mem_row_major);
    wmma::store_matrix_sync(smf + (size_t)(mi * 32 + 16) * 64 + ni * 32 + 16, a11, 64, wmma::mem_row_major);
    __syncthreads();
    if (wE) waitflag(wE, vE);
    if (pxf) {
        if (threadIdx.x == 0) {
            volatile unsigned* p = pxf;
            while (*p < vP) { }
            __threadfence();
        }
        __syncthreads();
    }

    const float* smf0 = (const float*)(smraw + SMFOFF);
    const float* smf1 = smf0 + 4096;
#pragma unroll
    for (int j = 0; j < 4; ++j) {
        int m = mb + 16 * j;
        float4 q0 = *(const float4*)(smf0 + (size_t)m * 64 + uloc * 4);
        float4 q1 = *(const float4*)(smf1 + (size_t)m * 64 + uloc * 4);
        float vi = q0.x + q1.x;
        float vf = q0.y + q1.y;
        float vg = q0.z + q1.z;
        float vo = q0.w + q1.w;
        if (pxsrc) {
            float4 p = __ldcg((const float4*)(pxsrc + (size_t)m * 64 + uloc * 4));
            vi += p.x; vf += p.y; vg += p.z; vo += p.w;
        }
        vi += badd[j * 4 + 0]; vf += badd[j * 4 + 1];
        vg += badd[j * 4 + 2]; vo += badd[j * 4 + 3];
        float cn = sigf(vf) * cst[j] + sigf(vi) * tanhf(vg);
        float h  = sigf(vo) * tanhf(cn);
        cst[j] = cn;
        __half hh = __float2half(h);
        size_t off = (size_t)(m0 + m) * HID + u0 + uloc;
        hout[off] = hh;
        if (hsave) hsave[off] = hh;
    }
}

// ---------------- pair partial: px = h[:,0:256] @ WX^T ----------------
__device__ void partial_step(char* smraw, uint32_t smb, const __half* __restrict__ h,
                             int m0, float* __restrict__ pxdst,
                             int kg, int mi, int ni, int uloc, int mb)
{
    stage_chunk(smb + AOFF, 0, 128, h, HID, HID, h, m0);
    cp_async_commit();
    stage_chunk(smb + AOFF + ABSZ, 128, 128, h, HID, HID, h, m0);
    cp_async_commit();
    cp_async_wait0();
    __syncthreads();

    wmma::fragment<wmma::accumulator, 16, 16, 16, float> a00, a01, a10, a11;
    wmma::fill_fragment(a00, 0.f);
    wmma::fill_fragment(a01, 0.f);
    wmma::fill_fragment(a10, 0.f);
    wmma::fill_fragment(a11, 0.f);
    wmma::fragment<wmma::matrix_a, 16, 16, 16, __half, wmma::row_major> af0, af1;
    wmma::fragment<wmma::matrix_b, 16, 16, 16, __half, wmma::col_major> bf0, bf1;
#pragma unroll
    for (int c = 0; c < 2; ++c) {
        const __half* abase = (const __half*)(smraw + AOFF + (size_t)c * ABSZ)
                            + (size_t)(mi * 32) * ASTRH;
        const __half* bbase = (const __half*)(smraw + WXOFF)
                            + (size_t)(ni * 32) * WXSTRH + c * 128;
#pragma unroll
        for (int s = 0; s < 4; ++s) {           // FIX: 4 slabs per k-group (was 2)
            int kk = (kg * 4 + s) << 4;         // covers all 128 cols of the chunk
            wmma::load_matrix_sync(af0, abase + kk, ASTRH);
            wmma::load_matrix_sync(af1, abase + 16 * ASTRH + kk, ASTRH);
            wmma::load_matrix_sync(bf0, bbase + kk, WXSTRH);
            wmma::load_matrix_sync(bf1, bbase + 16 * WXSTRH + kk, WXSTRH);
            wmma::mma_sync(a00, af0, bf0, a00);
            wmma::mma_sync(a01, af0, bf1, a01);
            wmma::mma_sync(a10, af1, bf0, a10);
            wmma::mma_sync(a11, af1, bf1, a11);
        }
    }
    float* smf = (float*)(smraw + SMFOFF) + (size_t)kg * 4096;
    wmma::store_matrix_sync(smf + (size_t)(mi * 32) * 64 + ni * 32,           a00, 64, wmma::mem_row_major);
    wmma::store_matrix_sync(smf + (size_t)(mi * 32) * 64 + ni * 32 + 16,      a01, 64, wmma::mem_row_major);
    wmma::store_matrix_sync(smf + (size_t)(mi * 32 + 16) * 64 + ni * 32,      a10, 64, wmma::mem_row_major);
    wmma::store_matrix_sync(smf + (size_t)(mi * 32 + 16) * 64 + ni * 32 + 16, a11, 64, wmma::mem_row_major);
    __syncthreads();
    const float* smf0 = (const float*)(smraw + SMFOFF);
    const float* smf1 = smf0 + 4096;
#pragma unroll
    for (int j = 0; j < 4; ++j) {
        int m = mb + 16 * j;
        float4 q0 = *(const float4*)(smf0 + (size_t)m * 64 + uloc * 4);
        float4 q1 = *(const float4*)(smf1 + (size_t)m * 64 + uloc * 4);
        float4 o;
        o.x = q0.x + q1.x; o.y = q0.y + q1.y; o.z = q0.z + q1.z; o.w = q0.w + q1.w;
        *(float4*)(pxdst + (size_t)m * 64 + uloc * 4) = o;
    }
}

// ---------------- persistent wavefront kernel ----------------
__global__ __launch_bounds__(256, 1) void lstm_hmma() {
    extern __shared__ char smraw[];
    uint32_t smb = smem_to_u32(smraw);
    int tid = threadIdx.x;
    int w = tid >> 5;
    int cta = blockIdx.x;
    int lb = cta & 63;
    bool top = (cta >= 64);
    int mh = lb >> 5;
    int m0 = mh * 64;
    int u0 = (lb & 31) * 16;
    int kg = w & 1;
    int mi = (w >> 1) & 1;
    int ni = w >> 2;
    int uloc = tid & 15;
    int mb = tid >> 4;

    float badd[16];
    float cst[4];

    // ===== encoder =====
    if (!top) {
        load_wsm(smraw, g_eWih0, INP, 0, INP, g_eWhh0, 576, u0);
        load_wx(smraw, g_eWih1, u0);
    } else {
        load_wsm(smraw, g_eWih1, HID, 256, 256, g_eWhh1, 768, u0);
    }
    {
        const float* bias = top ? g_be1 : g_be0;
#pragma unroll
        for (int j = 0; j < 4; ++j)
#pragma unroll
            for (int g = 0; g < 4; ++g)
                badd[j * 4 + g] = bias[g * 512 + u0 + uloc];
    }
#pragma unroll
    for (int j = 0; j < 4; ++j) cst[j] = 0.f;
    __syncthreads();

    unsigned* fb = &g_flag[0 + mh];
    unsigned* ft = &g_flag[2 + mh];

    if (!top) {
        for (int t = 0; t < TT; ++t) {
            waitflag(fb, 32u * (unsigned)t);
            cell_step(smraw, smb, g_x16 + (size_t)t * BSZ * INP, INP, INP,
                      g_h0[(t + 1) & 1], 576, badd, cst,
                      g_h0[t & 1], (__half*)0, m0, u0, kg, mi, ni, uloc, mb,
                      (unsigned*)0, 0u,
                      (t >= 2) ? ft : (unsigned*)0, 32u * (unsigned)(t - 1),
                      (unsigned*)0, 0u, (const float*)0);
            post_flag(fb);
            waitflag(fb, 32u * (unsigned)(t + 1));
            partial_step(smraw, smb, g_h0[t & 1], m0,
                         g_px + (size_t)(t & 1) * 262144 + (size_t)lb * 4096,
                         kg, mi, ni, uloc, mb);
            __syncthreads();
            if (tid == 0) {
                __threadfence();
                *(volatile unsigned*)&g_pxf[lb] = (unsigned)(t + 1);
            }
        }
    } else {
        for (int t = 0; t < TT; ++t) {
            waitflag(fb, 32u * (unsigned)(t + 1));
            cell_step(smraw, smb, g_h0[t & 1] + 256, HID, 256,
                      g_h1[(t + 1) & 1], 768, badd, cst,
                      g_h1[t & 1], (__half*)0, m0, u0, kg, mi, ni, uloc, mb,
                      ft, 32u * (unsigned)t,
                      (unsigned*)0, 0u,
                      &g_pxf[lb], (unsigned)(t + 1),
                      g_px + (size_t)(t & 1) * 262144 + (size_t)lb * 4096);
            post_flag(ft);
        }
    }

    grid_sync(NCTA);

    // ===== gx = z @ dWih0^T (z = encoder h1 at t=127, parity 1) =====
    {
        wmma::fragment<wmma::accumulator, 16, 16, 16, float> acc1;
        wmma::fill_fragment(acc1, 0.f);
        wmma::fragment<wmma::matrix_a, 16, 16, 16, __half, wmma::row_major> af;
        wmma::fragment<wmma::matrix_b, 16, 16, 16, __half, wmma::col_major> bfx;
        const __half* ap = g_h1[1] + (size_t)(w * 16) * HID;
        const __half* bp = g_dWih0 + (size_t)(cta * 16) * HID;
#pragma unroll 4
        for (int k0 = 0; k0 < HID; k0 += 16) {
            wmma::load_matrix_sync(af, ap + k0, HID);
            wmma::load_matrix_sync(bfx, bp + k0, HID);
            wmma::mma_sync(acc1, af, bfx, acc1);
        }
        wmma::store_matrix_sync(g_gx + (size_t)(w * 16) * G4 + cta * 16, acc1,
                                G4, wmma::mem_row_major);
    }
    grid_sync(2 * NCTA);

    // ===== decoder =====
    if (!top) {
        load_wsm(smraw, g_dWhh0, HID, 0, 0, g_dWhh0, 512, u0);
        load_wx(smraw, g_dWih1, u0);
#pragma unroll
        for (int j = 0; j < 4; ++j)
#pragma unroll
            for (int g = 0; g < 4; ++g) {
                int colg = g * 512 + u0 + uloc;
                badd[j * 4 + g] = g_bd0[colg]
                                + g_gx[(size_t)(m0 + mb + 16 * j) * G4 + colg];
            }
    } else {
        load_wsm(smraw, g_dWih1, HID, 256, 256, g_dWhh1, 768, u0);
#pragma unroll
        for (int j = 0; j < 4; ++j)
#pragma unroll
            for (int g = 0; g < 4; ++g)
                badd[j * 4 + g] = g_bd1[g * 512 + u0 + uloc];
    }
#pragma unroll
    for (int j = 0; j < 4; ++j) cst[j] = 0.f;
    __syncthreads();

    unsigned* fbd = &g_flag[4 + mh];
    unsigned* ftd = &g_flag[6 + mh];

    if (!top) {
        for (int t = 0; t < TT; ++t) {
            waitflag(fbd, 32u * (unsigned)t);
            cell_step(smraw, smb, g_hd0[(t + 1) & 1], HID, 0,
                      g_hd0[(t + 1) & 1], HID, badd, cst,
                      g_hd0[t & 1], (__half*)0, m0, u0, kg, mi, ni, uloc, mb,
                      (unsigned*)0, 0u,
                      (t >= 2) ? ftd : (unsigned*)0, 32u * (unsigned)(t - 1),
                      (unsigned*)0, 0u, (const float*)0);
            post_flag(fbd);
            waitflag(fbd, 32u * (unsigned)(t + 1));
            partial_step(smraw, smb, g_hd0[t & 1], m0,
                         g_px + (size_t)(t & 1) * 262144 + (size_t)lb * 4096,
                         kg, mi, ni, uloc, mb);
            __syncthreads();
            if (tid == 0) {
                __threadfence();
                *(volatile unsigned*)&g_pxf[64 + lb] = (unsigned)(t + 1);
            }
        }
    } else {
        for (int t = 0; t < TT; ++t) {
            waitflag(fbd, 32u * (unsigned)(t + 1));
            cell_step(smraw, smb, g_hd0[t & 1] + 256, HID, 256,
                      g_hd1[(t + 1) & 1], 768, badd, cst,
                      g_hd1[t & 1], g_hs + (size_t)t * BSZ * HID,
                      m0, u0, kg, mi, ni, uloc, mb,
                      ftd, 32u * (unsigned)t,
                      (unsigned*)0, 0u,
                      &g_pxf[64 + lb], (unsigned)(t + 1),
                      g_px + (size_t)(t & 1) * 262144 + (size_t)lb * 4096);
            post_flag(ftd);
        }
    }
}

// ---------------- FC head ----------------
__global__ __launch_bounds__(128) void fc_kernel(const float* __restrict__ fcb,
                                                 float* __restrict__ out) {
    int m0 = blockIdx.x * 64;
    int w = threadIdx.x >> 5;

    wmma::fragment<wmma::accumulator, 16, 16, 16, float> acc[4];
#pragma unroll
    for (int mt = 0; mt < 4; mt++) wmma::fill_fragment(acc[mt], 0.f);
    wmma::fragment<wmma::matrix_a, 16, 16, 16, __half, wmma::row_major> af;
    wmma::fragment<wmma::matrix_b, 16, 16, 16, __half, wmma::col_major> bf;

    const __half* Wb = g_fcW + (size_t)(w * 16) * HID;
    for (int k0 = 0; k0 < HID; k0 += 16) {
        wmma::load_matrix_sync(bf, Wb + k0, HID);
#pragma unroll
        for (int mt = 0; mt < 4; mt++) {
            wmma::load_matrix_sync(af, g_hs + (size_t)(m0 + mt * 16) * HID + k0, HID);
            wmma::mma_sync(acc[mt], af, bf, acc[mt]);
        }
    }

    __shared__ float sm[64][64];
#pragma unroll
    for (int mt = 0; mt < 4; mt++) {
        wmma::store_matrix_sync(&sm[mt * 16][w * 16], acc[mt], 64, wmma::mem_row_major);
    }
    __syncthreads();

    for (int idx = threadIdx.x; idx < 4096; idx += 128) {
        int m = idx >> 6;
        int i = idx & 63;
        int gm = m0 + m;
        int b = gm & (BSZ - 1);
        int t = gm >> 7;
        out[(size_t)b * TT * INP + (size_t)t * INP + i] = sm[m][i] + fcb[i];
    }
}

// ---------------- launch ----------------
extern "C" void kernel_launch(void* const* d_in, const int* in_sizes, int n_in,
                              void* d_out, int out_size) {
    (void)in_sizes; (void)n_in; (void)out_size;
    const float* x      = (const float*)d_in[0];
    const float* eWih0  = (const float*)d_in[1];
    const float* eWhh0  = (const float*)d_in[2];
    const float* ebih0  = (const float*)d_in[3];
    const float* ebhh0  = (const float*)d_in[4];
    const float* eWih1  = (const float*)d_in[5];
    const float* eWhh1  = (const float*)d_in[6];
    const float* ebih1  = (const float*)d_in[7];
    const float* ebhh1  = (const float*)d_in[8];
    const float* dWih0  = (const float*)d_in[9];
    const float* dWhh0  = (const float*)d_in[10];
    const float* dbih0  = (const float*)d_in[11];
    const float* dbhh0  = (const float*)d_in[12];
    const float* dWih1  = (const float*)d_in[13];
    const float* dWhh1  = (const float*)d_in[14];
    const float* dbih1  = (const float*)d_in[15];
    const float* dbhh1  = (const float*)d_in[16];
    const float* fcW    = (const float*)d_in[17];
    const float* fcb    = (const float*)d_in[18];
    float* out = (float*)d_out;

    cudaFuncSetAttribute(lstm_hmma,
                         cudaFuncAttributeMaxDynamicSharedMemorySize, SMEM_TOTAL);

    prep_kernel<<<2048, 256>>>(x, eWih0, eWhh0, ebih0, ebhh0,
                               eWih1, eWhh1, ebih1, ebhh1,
                               dWih0, dWhh0, dbih0, dbhh0,
                               dWih1, dWhh1, dbih1, dbhh1, fcW);

    lstm_hmma<<<NCTA, 256, SMEM_TOTAL>>>();

    fc_kernel<<<256, 128>>>(fcb, out);
}

// round 14
// speedup vs baseline: 1.1555x; 1.1555x over previous
#include <cstdint>
#include <cstddef>
#include <cuda_runtime.h>
#include <cuda_fp16.h>
#include <mma.h>

using namespace nvcuda;

#define BSZ 128
#define TT  128
#define INP 64
#define HID 512
#define G4  2048
#define HB  (BSZ*HID)
#define NCTA 128

// smem map (bytes):
//   [0, 37376)         B bottom: 32 rows x <=576 halves, stride 584h (1168B)
//   [37376, 103424)    B top:    32 rows x 1024 halves, stride 1032h (2064B)
//   [103424, 171008)   A ring: 2 x 33792B (64 rows x 256 halves, stride 264h/528B)
//   [171008, 187392)   smf: 64x64 float
#define BBOT    0
#define BSTRH   584
#define BSTRB   1168
#define BTOP    37376
#define TSTRH   1032
#define TSTRB   2064
#define AOFF    103424
#define ASTRH   264
#define ASTRB   528
#define ABSZ    33792
#define SMFOFF  171008
#define SMEM_TOTAL 187392

__device__ __align__(128) __half g_eWih0[G4*INP];
__device__ __align__(128) __half g_eWhh0[G4*HID];
__device__ __align__(128) __half g_eWih1[G4*HID];
__device__ __align__(128) __half g_eWhh1[G4*HID];
__device__ __align__(128) __half g_dWih0[G4*HID];
__device__ __align__(128) __half g_dWhh0[G4*HID];
__device__ __align__(128) __half g_dWih1[G4*HID];
__device__ __align__(128) __half g_dWhh1[G4*HID];
__device__ __align__(128) __half g_fcW[INP*HID];
__device__ float  g_be0[G4];
__device__ float  g_be1[G4];
__device__ float  g_bd0[G4];
__device__ float  g_bd1[G4];
__device__ __align__(128) __half g_x16[TT*BSZ*INP];
__device__ __align__(128) __half g_h0[2][HB];
__device__ __align__(128) __half g_h1[2][HB];
__device__ __align__(128) __half g_hd0[2][HB];
__device__ __align__(128) __half g_hd1[2][HB];
__device__ float  g_gx[BSZ*G4];
__device__ __align__(128) __half g_hs[TT*BSZ*HID];
__device__ unsigned g_ctr;
__device__ unsigned g_flag[4];   // [enc mh0, enc mh1, dec mh0, dec mh1]

// ---------------- prep ----------------
__global__ void prep_kernel(
    const float* __restrict__ x,
    const float* __restrict__ eWih0, const float* __restrict__ eWhh0,
    const float* __restrict__ ebih0, const float* __restrict__ ebhh0,
    const float* __restrict__ eWih1, const float* __restrict__ eWhh1,
    const float* __restrict__ ebih1, const float* __restrict__ ebhh1,
    const float* __restrict__ dWih0, const float* __restrict__ dWhh0,
    const float* __restrict__ dbih0, const float* __restrict__ dbhh0,
    const float* __restrict__ dWih1, const float* __restrict__ dWhh1,
    const float* __restrict__ dbih1, const float* __restrict__ dbhh1,
    const float* __restrict__ fcW)
{
    const long NP = 8822789;
    long stride = (long)gridDim.x * blockDim.x;
    for (long i = (long)blockIdx.x * blockDim.x + threadIdx.x; i < NP; i += stride) {
        long r = i;
        if (r < 131072)  { g_eWih0[r] = __float2half(eWih0[r]); continue; } r -= 131072;
        if (r < 1048576) { g_eWhh0[r] = __float2half(eWhh0[r]); continue; } r -= 1048576;
        if (r < 1048576) { g_eWih1[r] = __float2half(eWih1[r]); continue; } r -= 1048576;
        if (r < 1048576) { g_eWhh1[r] = __float2half(eWhh1[r]); continue; } r -= 1048576;
        if (r < 1048576) { g_dWih0[r] = __float2half(dWih0[r]); continue; } r -= 1048576;
        if (r < 1048576) { g_dWhh0[r] = __float2half(dWhh0[r]); continue; } r -= 1048576;
        if (r < 1048576) { g_dWih1[r] = __float2half(dWih1[r]); continue; } r -= 1048576;
        if (r < 1048576) { g_dWhh1[r] = __float2half(dWhh1[r]); continue; } r -= 1048576;
        if (r < 32768)   { g_fcW[r]   = __float2half(fcW[r]);   continue; } r -= 32768;
        if (r < 8192) {
            int which = (int)(r >> 11);
            int j = (int)(r & 2047);
            if      (which == 0) g_be0[j] = ebih0[j] + ebhh0[j];
            else if (which == 1) g_be1[j] = ebih1[j] + ebhh1[j];
            else if (which == 2) g_bd0[j] = dbih0[j] + dbhh0[j];
            else                 g_bd1[j] = dbih1[j] + dbhh1[j];
            continue;
        } r -= 8192;
        if (r < 1048576) {
            int t = (int)(r >> 13);
            int rem = (int)(r & 8191);
            int b = rem >> 6;
            int k = rem & 63;
            g_x16[r] = __float2half(x[(size_t)b * TT * INP + (size_t)t * INP + k]);
            continue;
        } r -= 1048576;
        if (r < 262144) {
            int which = (int)(r >> 16);
            int j = (int)(r & 65535);
            __half z = __float2half(0.f);
            if      (which == 0) g_h0[1][j]  = z;
            else if (which == 1) g_h1[1][j]  = z;
            else if (which == 2) g_hd0[1][j] = z;
            else                 g_hd1[1][j] = z;
            continue;
        } r -= 262144;
        {   // 5 sync words
            if (r < 4) g_flag[r] = 0u;
            else       g_ctr = 0u;
        }
    }
}

// ---------------- helpers ----------------
__device__ __forceinline__ void cp_async16(uint32_t dst_smem, const void* src) {
    asm volatile("cp.async.cg.shared.global [%0], [%1], 16;"
                 :: "r"(dst_smem), "l"(src) : "memory");
}
__device__ __forceinline__ void cp_async_commit() {
    asm volatile("cp.async.commit_group;" ::: "memory");
}
__device__ __forceinline__ void cp_async_wait0() {
    asm volatile("cp.async.wait_group 0;" ::: "memory");
}
__device__ __forceinline__ void cp_async_wait1() {
    asm volatile("cp.async.wait_group 1;" ::: "memory");
}
__device__ __forceinline__ uint32_t smem_to_u32(const void* smem_ptr) {
    uint32_t addr;
    asm("{ .reg .u64 tmp; cvta.to.shared.u64 tmp, %1; cvt.u32.u64 %0, tmp; }"
        : "=r"(addr) : "l"(smem_ptr));
    return addr;
}
__device__ __forceinline__ float sigf(float v) { return 1.f / (1.f + __expf(-v)); }

__device__ __forceinline__ void grid_sync(unsigned target) {
    __syncthreads();
    if (threadIdx.x == 0) {
        __threadfence();
        atomicAdd(&g_ctr, 1u);
        volatile unsigned* cp = &g_ctr;
        while (*cp < target) { }
        __threadfence();
    }
    __syncthreads();
}
__device__ __forceinline__ void waitflag(unsigned* f, unsigned v) {
    if (threadIdx.x == 0) {
        volatile unsigned* p = f;
        while (*p < v) { }
        __threadfence();
    }
    __syncthreads();
}
__device__ __forceinline__ void post_flag(unsigned* f) {
    __syncthreads();
    if (threadIdx.x == 0) {
        __threadfence();
        atomicAdd(f, 1u);
    }
}

// ---------------- stationary weight load into one B region ----------------
// region row c: weight row grow = (c&3)*512 + u0 + (c>>2); row data = [W1 | W2]
__device__ void load_B(char* smraw, int off, int strB,
                       const __half* __restrict__ W1, int ld1, int K1,
                       const __half* __restrict__ W2, int Ktot, int u0) {
    int ng = Ktot >> 3;
    int tot = 32 * ng;
    for (int idx = threadIdx.x; idx < tot; idx += 256) {
        int c = idx / ng;
        int gi = idx - c * ng;
        int k = gi << 3;
        int grow = (c & 3) * 512 + u0 + (c >> 2);
        uint4 v;
        if (k < K1) v = *(const uint4*)(W1 + (size_t)grow * ld1 + k);
        else        v = *(const uint4*)(W2 + (size_t)grow * 512 + (k - K1));
        *(uint4*)(smraw + off + (size_t)c * strB + ((size_t)k << 1)) = v;
    }
}

// ---------------- stage one A chunk (cols 256 or 64) from 3 regions ----------------
// region0: A cols [0,bx) from sx (ld ldx); region1: [bx,b1) from s1 (ld 512);
// region2: [b1,..) from s2 (ld 512).
__device__ __forceinline__ void stage3(uint32_t dst, int kb, int cols,
                                       const __half* __restrict__ sx, int ldx, int bx,
                                       const __half* __restrict__ s1, int b1,
                                       const __half* __restrict__ s2, int m0) {
    int sh = (cols == 256) ? 5 : 3;
    int msk = (1 << sh) - 1;
    int tot = cols << 3;    // 64 rows * cols/8 granules
    for (int idx = threadIdx.x; idx < tot; idx += 256) {
        int r = idx >> sh;
        int gi = idx & msk;
        int k = kb + (gi << 3);
        const __half* src;
        if (k < bx)      src = sx + (size_t)(m0 + r) * ldx + k;
        else if (k < b1) src = s1 + (size_t)(m0 + r) * HID + (k - bx);
        else             src = s2 + (size_t)(m0 + r) * HID + (k - b1);
        cp_async16(dst + (uint32_t)(r * ASTRB + (gi << 4)), src);
    }
}

// ---------------- fused dual-layer period step ----------------
// CTA: 64 batch rows x 64 gate-cols (cols 0-31 bottom layer, 32-63 top layer).
// Warps: L = w>>2 (bottom/top), mi = (w>>1)&1, ni = w&1 -> 32x16 warp tiles.
// Bottom consumes A-cols [0,KB0); top consumes A-cols [offT, KA).
__device__ __forceinline__ void period_step(
    char* smraw, uint32_t smb,
    int KA, int KB0, int offT, int NCH,
    const __half* __restrict__ sx, int ldx, int bx,
    const __half* __restrict__ s1, int b1,
    const __half* __restrict__ s2,
    const float* badd, float* cst,
    __half* __restrict__ hbot, __half* __restrict__ htop,
    __half* __restrict__ hsave,
    bool doBot, bool doTop,
    int m0, int u0, int L, int mi, int ni, int uloc, int mb)
{
    wmma::fragment<wmma::accumulator, 16, 16, 16, float> acc0, acc1;
    wmma::fill_fragment(acc0, 0.f);
    wmma::fill_fragment(acc1, 0.f);
    wmma::fragment<wmma::matrix_a, 16, 16, 16, __half, wmma::row_major> af0, af1;
    wmma::fragment<wmma::matrix_b, 16, 16, 16, __half, wmma::col_major> bf;

    {
        int c0 = (KA < 256) ? KA : 256;
        stage3(smb + AOFF, 0, c0, sx, ldx, bx, s1, b1, s2, m0);
        cp_async_commit();
    }
    const int kA0 = L ? offT : 0;
    const int kAe = L ? KA : KB0;
    const int bstr = L ? TSTRH : BSTRH;
    const __half* bregion = (const __half*)(smraw + (L ? BTOP : BBOT))
                          + (size_t)(ni * 16) * bstr;
    const int bs = L ? offT : 0;

    for (int i = 0; i < NCH; ++i) {
        int kb = i << 8;
        int ke = kb + 256; if (ke > KA) ke = KA;
        if (i + 1 < NCH) {
            int kb2 = (i + 1) << 8;
            int c2 = KA - kb2; if (c2 > 256) c2 = 256;
            stage3(smb + AOFF + (uint32_t)(((i + 1) & 1) * ABSZ), kb2, c2,
                   sx, ldx, bx, s1, b1, s2, m0);
            cp_async_commit();
            cp_async_wait1();
        } else {
            cp_async_wait0();
        }
        __syncthreads();
        const __half* ab = (const __half*)(smraw + AOFF + (size_t)((i & 1) * ABSZ))
                         + (size_t)(mi * 32) * ASTRH;
        int lo = (kb > kA0) ? kb : kA0;
        int hi = (ke < kAe) ? ke : kAe;
#pragma unroll 4
        for (int k = lo; k < hi; k += 16) {
            wmma::load_matrix_sync(af0, ab + (k - kb), ASTRH);
            wmma::load_matrix_sync(af1, ab + 16 * ASTRH + (k - kb), ASTRH);
            wmma::load_matrix_sync(bf, bregion + (k - bs), bstr);
            wmma::mma_sync(acc0, af0, bf, acc0);
            wmma::mma_sync(acc1, af1, bf, acc1);
        }
        __syncthreads();
    }

    float* smf = (float*)(smraw + SMFOFF);
    int colb = L * 32 + ni * 16;
    wmma::store_matrix_sync(smf + (size_t)(mi * 32) * 64 + colb, acc0, 64,
                            wmma::mem_row_major);
    wmma::store_matrix_sync(smf + (size_t)(mi * 32 + 16) * 64 + colb, acc1, 64,
                            wmma::mem_row_major);
    __syncthreads();

    bool act = (uloc < 8) ? doBot : doTop;
    if (act) {
        int ul = uloc & 7;
        int base = ((uloc >> 3) << 5) + ul * 4;
        __half* hout = (uloc < 8) ? hbot : htop;
#pragma unroll
        for (int j = 0; j < 4; ++j) {
            int m = mb + 16 * j;
            float4 q = *(const float4*)(smf + (size_t)m * 64 + base);
            float vi = q.x + badd[j * 4 + 0];
            float vf = q.y + badd[j * 4 + 1];
            float vg = q.z + badd[j * 4 + 2];
            float vo = q.w + badd[j * 4 + 3];
            float cn = sigf(vf) * cst[j] + sigf(vi) * tanhf(vg);
            float h  = sigf(vo) * tanhf(cn);
            cst[j] = cn;
            __half hh = __float2half(h);
            size_t off = (size_t)(m0 + m) * HID + u0 + ul;
            hout[off] = hh;
            if (uloc >= 8 && hsave) hsave[off] = hh;
        }
    }
}

// ---------------- persistent fused wavefront kernel ----------------
__global__ __launch_bounds__(256, 1) void lstm_hmma() {
    extern __shared__ char smraw[];
    uint32_t smb = smem_to_u32(smraw);
    int tid = threadIdx.x;
    int w = tid >> 5;
    int cta = blockIdx.x;
    int mh = cta >> 6;              // batch-half group (64 CTAs each)
    int lb = cta & 63;
    int m0 = mh * 64;
    int u0 = lb * 8;                // 8 units per layer per CTA
    int L = w >> 2;                 // 0 = bottom layer warps, 1 = top
    int mi = (w >> 1) & 1;
    int ni = w & 1;
    int uloc = tid & 15;            // 0-7 bottom unit, 8-15 top unit
    int mb = tid >> 4;

    float badd[16];
    float cst[4];

    // ===== encoder phase =====
    load_B(smraw, BBOT, BSTRB, g_eWih0, INP, INP, g_eWhh0, 576, u0);
    load_B(smraw, BTOP, TSTRB, g_eWih1, HID, HID, g_eWhh1, 1024, u0);
    {
#pragma unroll
        for (int j = 0; j < 4; ++j)
#pragma unroll
            for (int g = 0; g < 4; ++g) {
                if (uloc < 8) badd[j * 4 + g] = g_be0[g * 512 + u0 + uloc];
                else          badd[j * 4 + g] = g_be1[g * 512 + u0 + (uloc - 8)];
            }
    }
#pragma unroll
    for (int j = 0; j < 4; ++j) cst[j] = 0.f;
    __syncthreads();

    unsigned* f = &g_flag[mh];
    for (int p = 0; p <= TT; ++p) {
        if (p) waitflag(f, 64u * (unsigned)p);
        const __half* sx = g_x16 + (size_t)((p < TT) ? p : (TT - 1)) * BSZ * INP;
        period_step(smraw, smb, 1088, 576, 64, 5,
                    sx, INP, 64,
                    g_h0[(p + 1) & 1], 576,
                    g_h1[p & 1],
                    badd, cst,
                    g_h0[p & 1], g_h1[(p + 1) & 1], (__half*)0,
                    p < TT, p >= 1,
                    m0, u0, L, mi, ni, uloc, mb);
        post_flag(f);
    }

    grid_sync(NCTA);

    // ===== gx = z @ dWih0^T (z = encoder h1 final, parity 1) =====
    {
        wmma::fragment<wmma::accumulator, 16, 16, 16, float> acc1;
        wmma::fill_fragment(acc1, 0.f);
        wmma::fragment<wmma::matrix_a, 16, 16, 16, __half, wmma::row_major> af;
        wmma::fragment<wmma::matrix_b, 16, 16, 16, __half, wmma::col_major> bfx;
        const __half* ap = g_h1[1] + (size_t)(w * 16) * HID;
        const __half* bp = g_dWih0 + (size_t)(cta * 16) * HID;
#pragma unroll 4
        for (int k0 = 0; k0 < HID; k0 += 16) {
            wmma::load_matrix_sync(af, ap + k0, HID);
            wmma::load_matrix_sync(bfx, bp + k0, HID);
            wmma::mma_sync(acc1, af, bfx, acc1);
        }
        wmma::store_matrix_sync(g_gx + (size_t)(w * 16) * G4 + cta * 16, acc1,
                                G4, wmma::mem_row_major);
    }
    grid_sync(2 * NCTA);

    // ===== decoder phase =====
    load_B(smraw, BBOT, BSTRB, g_dWhh0, HID, 0, g_dWhh0, 512, u0);
    load_B(smraw, BTOP, TSTRB, g_dWih1, HID, HID, g_dWhh1, 1024, u0);
    {
#pragma unroll
        for (int j = 0; j < 4; ++j)
#pragma unroll
            for (int g = 0; g < 4; ++g) {
                if (uloc < 8) {
                    int col = g * 512 + u0 + uloc;
                    badd[j * 4 + g] = g_bd0[col]
                                    + g_gx[(size_t)(m0 + mb + 16 * j) * G4 + col];
                } else {
                    badd[j * 4 + g] = g_bd1[g * 512 + u0 + (uloc - 8)];
                }
            }
    }
#pragma unroll
    for (int j = 0; j < 4; ++j) cst[j] = 0.f;
    __syncthreads();

    unsigned* f2 = &g_flag[2 + mh];
    for (int p = 0; p <= TT; ++p) {
        if (p) waitflag(f2, 64u * (unsigned)p);
        period_step(smraw, smb, 1024, 512, 0, 4,
                    (const __half*)0, 1, 0,
                    g_hd0[(p + 1) & 1], 512,
                    g_hd1[p & 1],
                    badd, cst,
                    g_hd0[p & 1], g_hd1[(p + 1) & 1],
                    (p >= 1) ? (g_hs + (size_t)(p - 1) * BSZ * HID) : (__half*)0,
                    p < TT, p >= 1,
                    m0, u0, L, mi, ni, uloc, mb);
        post_flag(f2);
    }
}

// ---------------- FC head ----------------
__global__ __launch_bounds__(128) void fc_kernel(const float* __restrict__ fcb,
                                                 float* __restrict__ out) {
    int m0 = blockIdx.x * 64;
    int w = threadIdx.x >> 5;

    wmma::fragment<wmma::accumulator, 16, 16, 16, float> acc[4];
#pragma unroll
    for (int mt = 0; mt < 4; mt++) wmma::fill_fragment(acc[mt], 0.f);
    wmma::fragment<wmma::matrix_a, 16, 16, 16, __half, wmma::row_major> af;
    wmma::fragment<wmma::matrix_b, 16, 16, 16, __half, wmma::col_major> bf;

    const __half* Wb = g_fcW + (size_t)(w * 16) * HID;
    for (int k0 = 0; k0 < HID; k0 += 16) {
        wmma::load_matrix_sync(bf, Wb + k0, HID);
#pragma unroll
        for (int mt = 0; mt < 4; mt++) {
            wmma::load_matrix_sync(af, g_hs + (size_t)(m0 + mt * 16) * HID + k0, HID);
            wmma::mma_sync(acc[mt], af, bf, acc[mt]);
        }
    }

    __shared__ float sm[64][64];
#pragma unroll
    for (int mt = 0; mt < 4; mt++) {
        wmma::store_matrix_sync(&sm[mt * 16][w * 16], acc[mt], 64, wmma::mem_row_major);
    }
    __syncthreads();

    for (int idx = threadIdx.x; idx < 4096; idx += 128) {
        int m = idx >> 6;
        int i = idx & 63;
        int gm = m0 + m;
        int b = gm & (BSZ - 1);
        int t = gm >> 7;
        out[(size_t)b * TT * INP + (size_t)t * INP + i] = sm[m][i] + fcb[i];
    }
}

// ---------------- launch ----------------
extern "C" void kernel_launch(void* const* d_in, const int* in_sizes, int n_in,
                              void* d_out, int out_size) {
    (void)in_sizes; (void)n_in; (void)out_size;
    const float* x      = (const float*)d_in[0];
    const float* eWih0  = (const float*)d_in[1];
    const float* eWhh0  = (const float*)d_in[2];
    const float* ebih0  = (const float*)d_in[3];
    const float* ebhh0  = (const float*)d_in[4];
    const float* eWih1  = (const float*)d_in[5];
    const float* eWhh1  = (const float*)d_in[6];
    const float* ebih1  = (const float*)d_in[7];
    const float* ebhh1  = (const float*)d_in[8];
    const float* dWih0  = (const float*)d_in[9];
    const float* dWhh0  = (const float*)d_in[10];
    const float* dbih0  = (const float*)d_in[11];
    const float* dbhh0  = (const float*)d_in[12];
    const float* dWih1  = (const float*)d_in[13];
    const float* dWhh1  = (const float*)d_in[14];
    const float* dbih1  = (const float*)d_in[15];
    const float* dbhh1  = (const float*)d_in[16];
    const float* fcW    = (const float*)d_in[17];
    const float* fcb    = (const float*)d_in[18];
    float* out = (float*)d_out;

    cudaFuncSetAttribute(lstm_hmma,
                         cudaFuncAttributeMaxDynamicSharedMemorySize, SMEM_TOTAL);

    prep_kernel<<<2048, 256>>>(x, eWih0, eWhh0, ebih0, ebhh0,
                               eWih1, eWhh1, ebih1, ebhh1,
                               dWih0, dWhh0, dbih0, dbhh0,
                               dWih1, dWhh1, dbih1, dbhh1, fcW);

    lstm_hmma<<<NCTA, 256, SMEM_TOTAL>>>();

    fc_kernel<<<256, 128>>>(fcb, out);
}